// round 15
// baseline (speedup 1.0000x reference)
#include <cuda_runtime.h>
#include <cuda_bf16.h>
#include <cstdint>

#define K_CODES 8192
#define D_DIM   256
#define N_Q     16384
#define HW      1024
#define MQ      128
#define CCH     128
#define NCHUNKS (K_CODES / CCH)
#define WIN     2e-4f
#define MAXCAND 16

// ---------------- device scratch ----------------
__device__ __nv_bfloat16 g_ztb[(size_t)N_Q * D_DIM];
__device__ float g_ztf[(size_t)N_Q * D_DIM];
__device__ __nv_bfloat16 g_cbb[(size_t)K_CODES * D_DIM];
__device__ float g_cbT[(size_t)D_DIM * K_CODES];
__device__ float g_c2[K_CODES];
__device__ float g_z2[N_Q];
__device__ int   g_ncand[N_Q];
__device__ int   g_cand[N_Q][MAXCAND];
__device__ int   g_idx[N_Q];

// ---------------- asm helpers ----------------
__device__ __forceinline__ uint32_t sm_u32(const void* p) {
    uint32_t a;
    asm("{ .reg .u64 t; cvta.to.shared.u64 t, %1; cvt.u32.u64 %0, t; }" : "=r"(a) : "l"(p));
    return a;
}
#define CP_ASYNC16(dst, src) \
    asm volatile("cp.async.cg.shared.global [%0], [%1], 16;" :: "r"(dst), "l"(src))
#define CP_COMMIT() asm volatile("cp.async.commit_group;" ::: "memory")
#define CP_WAIT(n)  asm volatile("cp.async.wait_group %0;" :: "n"(n) : "memory")

__device__ __forceinline__ void ldsm_x4(uint32_t& r0, uint32_t& r1, uint32_t& r2,
                                        uint32_t& r3, uint32_t addr) {
    asm volatile("ldmatrix.sync.aligned.m8n8.x4.shared.b16 {%0,%1,%2,%3}, [%4];"
                 : "=r"(r0), "=r"(r1), "=r"(r2), "=r"(r3) : "r"(addr));
}
__device__ __forceinline__ void ldsm_x2(uint32_t& r0, uint32_t& r1, uint32_t addr) {
    asm volatile("ldmatrix.sync.aligned.m8n8.x2.shared.b16 {%0,%1}, [%2];"
                 : "=r"(r0), "=r"(r1) : "r"(addr));
}
__device__ __forceinline__ void mma_bf16(float& d0, float& d1, float& d2, float& d3,
                                         uint32_t a0, uint32_t a1, uint32_t a2, uint32_t a3,
                                         uint32_t b0, uint32_t b1) {
    asm volatile("mma.sync.aligned.m16n8k16.row.col.f32.bf16.bf16.f32 "
                 "{%0,%1,%2,%3},{%4,%5,%6,%7},{%8,%9},{%0,%1,%2,%3};"
                 : "+f"(d0), "+f"(d1), "+f"(d2), "+f"(d3)
                 : "r"(a0), "r"(a1), "r"(a2), "r"(a3), "r"(b0), "r"(b1));
}
__device__ __forceinline__ uint32_t swz(uint32_t r, uint32_t u) {
    return r * 512u + ((u ^ (r & 7u)) << 4);
}

// ---------------- kernel 1: codebook prep ----------------
__global__ void k_prep_code(const float* __restrict__ cb) {
    int bx = blockIdx.x, t = threadIdx.x;
    if (bx < 2048) {
        int i = bx * 256 + t;
        float4 v = ((const float4*)cb)[i];
        ((__nv_bfloat162*)g_cbb)[i * 2] =
            __nv_bfloat162(__float2bfloat16(v.x), __float2bfloat16(v.y));
        ((__nv_bfloat162*)g_cbb)[i * 2 + 1] =
            __nv_bfloat162(__float2bfloat16(v.z), __float2bfloat16(v.w));
    } else if (bx < 4096) {
        __shared__ float tile[32][33];
        int bb = bx - 2048;
        int k0 = (bb & 255) * 32, d0 = (bb >> 8) * 32;
        int tx = t & 31, ty = t >> 5;
#pragma unroll
        for (int j = 0; j < 32; j += 8)
            tile[ty + j][tx] = cb[(size_t)(k0 + ty + j) * D_DIM + d0 + tx];
        __syncthreads();
#pragma unroll
        for (int j = 0; j < 32; j += 8)
            g_cbT[(size_t)(d0 + ty + j) * K_CODES + k0 + tx] = tile[tx][ty + j];
    } else {
        // exact c2 (proven round-1 arithmetic)
        int w = ((bx - 4096) * 256 + t) >> 5;
        int lane = t & 31;
        if (w >= K_CODES) return;
        float s = 0.f;
#pragma unroll
        for (int i = 0; i < 8; i++) {
            float v = cb[(size_t)w * D_DIM + lane + i * 32];
            s = __fadd_rn(s, __fmul_rn(v, v));
        }
#pragma unroll
        for (int o = 16; o; o >>= 1) s = __fadd_rn(s, __shfl_xor_sync(0xffffffffu, s, o));
        if (lane == 0) g_c2[w] = s;
    }
}

// ---------------- kernel 2: z prep + exact z2 ----------------
__global__ void k_prep_z(const float* __restrict__ z) {
    int bx = blockIdx.x, t = threadIdx.x;
    if (bx < 4096) {
        __shared__ float tile[32][33];
        int h0 = (bx & 31) * 32, d0 = ((bx >> 5) & 7) * 32, b = bx >> 8;
        int tx = t & 31, ty = t >> 5;
#pragma unroll
        for (int j = 0; j < 32; j += 8)
            tile[ty + j][tx] = z[(size_t)(b * D_DIM + d0 + ty + j) * HW + h0 + tx];
        __syncthreads();
#pragma unroll
        for (int j = 0; j < 32; j += 8) {
            int q = b * HW + h0 + ty + j, d = d0 + tx;
            float vv = tile[tx][ty + j];
            g_ztf[(size_t)q * D_DIM + d] = vv;
            g_ztb[(size_t)q * D_DIM + d] = __float2bfloat16(vv);
        }
    } else {
        // exact z2 (proven round-1 arithmetic)
        int q = (bx - 4096) * 256 + t;
        int b = q >> 10, hw = q & 1023;
        const float* p = z + (size_t)b * (D_DIM * HW) + hw;
        float s = 0.f;
        for (int d = 0; d < D_DIM; d++) {
            float v = p[(size_t)d * HW];
            s = __fadd_rn(s, __fmul_rn(v, v));
        }
        g_z2[q] = s;
    }
}

// ---------------- kernel 3: main HMMA (unchanged) ----------------
__global__ __launch_bounds__(512, 1) void k_mma() {
    extern __shared__ char sraw[];
    uint32_t raw32 = sm_u32(sraw);
    uint32_t pad = (1024u - (raw32 & 1023u)) & 1023u;
    char* base = sraw + pad;
    const uint32_t sA = raw32 + pad;
    const uint32_t sB0 = sA + 65536u, sB1 = sB0 + 65536u;

    const int t = threadIdx.x, lane = t & 31, w = t >> 5;
    const int mw = w >> 2;
    const int nw = w & 3;
    const int q0 = blockIdx.x * MQ;

    {
        const char* src = (const char*)(g_cbb);
#pragma unroll
        for (int i = 0; i < 8; i++) {
            int idx = i * 512 + t;
            uint32_t r = (uint32_t)(idx >> 5), u = (uint32_t)(idx & 31);
            CP_ASYNC16(sB0 + swz(r, u), src + (size_t)idx * 16);
        }
        CP_COMMIT();
    }
    {
        const int4* src = (const int4*)(g_ztb + (size_t)q0 * D_DIM);
#pragma unroll
        for (int i = 0; i < 8; i++) {
            int idx = i * 512 + t;
            uint32_t r = (uint32_t)(idx >> 5), u = (uint32_t)(idx & 31);
            *(int4*)(base + swz(r, u)) = src[idx];
        }
    }

    float v1[4], v2[4], v3[4];
    int   k1[4], k2[4], k3[4];
#pragma unroll
    for (int i = 0; i < 4; i++) {
        v1[i] = __int_as_float(0x7f800000); v2[i] = v1[i]; v3[i] = v1[i];
        k1[i] = 0x7fffffff; k2[i] = k1[i]; k3[i] = k1[i];
    }

    uint32_t aRow[2], aR7[2];
#pragma unroll
    for (int mi = 0; mi < 2; mi++) {
        uint32_t r = (uint32_t)(mw * 32 + mi * 16 + (lane & 15));
        aRow[mi] = sA + r * 512u;
        aR7[mi] = r & 7u;
    }
    const uint32_t aU = (uint32_t)(lane >> 4);
    const uint32_t bRl = (uint32_t)(nw * 32 + (lane & 7));
    const uint32_t bU = (uint32_t)((lane >> 3) & 1);

    for (int ch = 0; ch < NCHUNKS; ch++) {
        if (ch + 1 < NCHUNKS) {
            uint32_t dstB = ((ch + 1) & 1) ? sB1 : sB0;
            const char* src = (const char*)(g_cbb + (size_t)(ch + 1) * CCH * D_DIM);
#pragma unroll
            for (int i = 0; i < 8; i++) {
                int idx = i * 512 + t;
                uint32_t r = (uint32_t)(idx >> 5), u = (uint32_t)(idx & 31);
                CP_ASYNC16(dstB + swz(r, u), src + (size_t)idx * 16);
            }
            CP_COMMIT();
            CP_WAIT(1);
        } else {
            CP_WAIT(0);
        }
        __syncthreads();

        const uint32_t sB = (ch & 1) ? sB1 : sB0;
        float acc[2][4][4];
#pragma unroll
        for (int mi = 0; mi < 2; mi++)
#pragma unroll
            for (int ni = 0; ni < 4; ni++)
#pragma unroll
                for (int e = 0; e < 4; e++) acc[mi][ni][e] = 0.f;

#pragma unroll
        for (int kk = 0; kk < 16; kk++) {
            uint32_t au = (uint32_t)(kk * 2) + aU;
            uint32_t af[2][4];
#pragma unroll
            for (int mi = 0; mi < 2; mi++)
                ldsm_x4(af[mi][0], af[mi][1], af[mi][2], af[mi][3],
                        aRow[mi] + ((au ^ aR7[mi]) << 4));
            uint32_t bu = (uint32_t)(kk * 2) + bU;
            uint32_t bf[4][2];
#pragma unroll
            for (int ni = 0; ni < 4; ni++) {
                uint32_t r = bRl + (uint32_t)(ni * 8);
                ldsm_x2(bf[ni][0], bf[ni][1], sB + r * 512u + ((bu ^ (r & 7u)) << 4));
            }
#pragma unroll
            for (int mi = 0; mi < 2; mi++)
#pragma unroll
                for (int ni = 0; ni < 4; ni++)
                    mma_bf16(acc[mi][ni][0], acc[mi][ni][1], acc[mi][ni][2], acc[mi][ni][3],
                             af[mi][0], af[mi][1], af[mi][2], af[mi][3],
                             bf[ni][0], bf[ni][1]);
        }

        const int kb = ch * CCH + nw * 32 + (lane & 3) * 2;
#pragma unroll
        for (int ni = 0; ni < 4; ni++) {
            float2 c2v = *(const float2*)(g_c2 + kb + ni * 8);
            int c0 = kb + ni * 8, c1 = c0 + 1;
#pragma unroll
            for (int mi = 0; mi < 2; mi++) {
#pragma unroll
                for (int half = 0; half < 2; half++) {
                    int sl = mi * 2 + half;
                    float s0 = __fmaf_rn(-2.f, acc[mi][ni][half * 2], c2v.x);
                    float s1 = __fmaf_rn(-2.f, acc[mi][ni][half * 2 + 1], c2v.y);
                    if (s0 < v3[sl]) {
                        if (s0 < v1[sl]) { v3[sl]=v2[sl];k3[sl]=k2[sl]; v2[sl]=v1[sl];k2[sl]=k1[sl]; v1[sl]=s0;k1[sl]=c0; }
                        else if (s0 < v2[sl]) { v3[sl]=v2[sl];k3[sl]=k2[sl]; v2[sl]=s0;k2[sl]=c0; }
                        else { v3[sl]=s0;k3[sl]=c0; }
                    }
                    if (s1 < v3[sl]) {
                        if (s1 < v1[sl]) { v3[sl]=v2[sl];k3[sl]=k2[sl]; v2[sl]=v1[sl];k2[sl]=k1[sl]; v1[sl]=s1;k1[sl]=c1; }
                        else if (s1 < v2[sl]) { v3[sl]=v2[sl];k3[sl]=k2[sl]; v2[sl]=s1;k2[sl]=c1; }
                        else { v3[sl]=s1;k3[sl]=c1; }
                    }
                }
            }
        }
        __syncthreads();
    }

    float2* cand = (float2*)(base + 65536);
#pragma unroll
    for (int sl = 0; sl < 4; sl++) {
        int ql = mw * 32 + (sl >> 1) * 16 + (sl & 1) * 8 + (lane >> 2);
        int e = nw * 12 + (lane & 3) * 3;
        cand[ql * 48 + e]     = make_float2(v1[sl], __int_as_float(k1[sl]));
        cand[ql * 48 + e + 1] = make_float2(v2[sl], __int_as_float(k2[sl]));
        cand[ql * 48 + e + 2] = make_float2(v3[sl], __int_as_float(k3[sl]));
    }
    __syncthreads();
    if (t < MQ) {
        float m1 = __int_as_float(0x7f800000);
#pragma unroll
        for (int e = 0; e < 48; e++) m1 = fminf(m1, cand[t * 48 + e].x);
        float lim = m1 + WIN;
        int overflow = 0;
#pragma unroll
        for (int e = 2; e < 48; e += 3) overflow |= (cand[t * 48 + e].x <= lim);
        int q = q0 + t;
        int n = 0;
        if (!overflow) {
#pragma unroll
            for (int e = 0; e < 48; e++) {
                if ((e % 3) == 2) continue;
                float2 c = cand[t * 48 + e];
                if (c.x <= lim && n < MAXCAND) g_cand[q][n++] = __float_as_int(c.y);
                else if (c.x <= lim) overflow = 1;
            }
        }
        g_ncand[q] = overflow ? -1 : n;
    }
}

// ---------------- kernel 4: exact fixup — one query per warp, smem-staged ----------------
// smem: rows[4][MAXCAND][257] + zrow[4][264]
__global__ __launch_bounds__(128) void k_fixup() {
    extern __shared__ float fsm[];
    const int t = threadIdx.x, lane = t & 31, w = t >> 5;
    const int q = blockIdx.x * 4 + w;
    float* rows = fsm + (size_t)w * MAXCAND * 257;       // this warp's candidate rows
    float* zrow = fsm + 4 * MAXCAND * 257 + w * 264;     // this warp's z row

    int n = g_ncand[q];
    float z2v = g_z2[q];
    float bv = __int_as_float(0x7f800000); int bk = 0x7fffffff;

    if (n < 0) {
        // full exact rescan, coalesced via g_cbT (proven R12, verbatim arithmetic)
        const float* zr = g_ztf + (size_t)q * D_DIM;
        for (int i = 0; i < 256; i += 4) {
            int ka = lane + i * 32, kb2 = ka + 32, kc = ka + 64, kd = ka + 96;
            float a0 = 0.f, a1 = 0.f, a2 = 0.f, a3 = 0.f;
            for (int d = 0; d < D_DIM; d++) {
                float zv = zr[d];
                const float* row = g_cbT + (size_t)d * K_CODES;
                a0 = __fmaf_rn(zv, row[ka], a0);
                a1 = __fmaf_rn(zv, row[kb2], a1);
                a2 = __fmaf_rn(zv, row[kc], a2);
                a3 = __fmaf_rn(zv, row[kd], a3);
            }
            float d0 = __fadd_rn(__fsub_rn(z2v, __fmul_rn(2.0f, a0)), g_c2[ka]);
            float d1 = __fadd_rn(__fsub_rn(z2v, __fmul_rn(2.0f, a1)), g_c2[kb2]);
            float d2 = __fadd_rn(__fsub_rn(z2v, __fmul_rn(2.0f, a2)), g_c2[kc]);
            float d3 = __fadd_rn(__fsub_rn(z2v, __fmul_rn(2.0f, a3)), g_c2[kd]);
            if (d0 < bv || (d0 == bv && ka < bk))  { bv = d0; bk = ka; }
            if (d1 < bv || (d1 == bv && kb2 < bk)) { bv = d1; bk = kb2; }
            if (d2 < bv || (d2 == bv && kc < bk))  { bv = d2; bk = kc; }
            if (d3 < bv || (d3 == bv && kd < bk))  { bv = d3; bk = kd; }
        }
    } else {
        // stage z row (coalesced, broadcast-friendly reads later)
        {
            const float4* zsrc = (const float4*)(g_ztf + (size_t)q * D_DIM);
            float4 a = zsrc[lane], b4 = zsrc[lane + 32];
            int d0 = lane * 4;
            zrow[d0] = a.x; zrow[d0 + 1] = a.y; zrow[d0 + 2] = a.z; zrow[d0 + 3] = a.w;
            zrow[d0 + 128] = b4.x; zrow[d0 + 129] = b4.y; zrow[d0 + 130] = b4.z; zrow[d0 + 131] = b4.w;
        }
        // stage candidate rows cooperatively (coalesced from row-major cb via g_cbT? use
        // original layout values: g_cbT[d][k] == cb[k][d]; load from cb row-major copy g_cbb? 
        // need fp32: use g_ztf-style source = reconstruct from g_cbT would be strided; instead
        // exact values also live in cb itself — but cb isn't passed; use g_cbT strided per lane?
        // Simplest coalesced fp32 source: g_cbT columns are strided; so stage from cbRow global:
        // we kept no row-major fp32 copy — reuse original input pointer passed via launch.
        // (handled below: k_fixup takes cb pointer)
        ;
        bk = bk; // placeholder, real work in k_fixup_main below
    }
    // NOTE: this kernel body is completed in k_fixup_cb (cb pointer needed); see below.
    if (n < 0) {
#pragma unroll
        for (int o = 16; o; o >>= 1) {
            float ov = __shfl_xor_sync(0xffffffffu, bv, o);
            int   ok = __shfl_xor_sync(0xffffffffu, bk, o);
            if (ov < bv || (ov == bv && ok < bk)) { bv = ov; bk = ok; }
        }
        if (lane == 0) g_idx[q] = bk;
    }
}

// candidate-path fixup with cb pointer (row-major fp32, coalesced staging)
__global__ __launch_bounds__(128) void k_fixup_cb(const float* __restrict__ cb) {
    extern __shared__ float fsm[];
    const int t = threadIdx.x, lane = t & 31, w = t >> 5;
    const int q = blockIdx.x * 4 + w;
    float* rows = fsm + (size_t)w * MAXCAND * 257;
    float* zrow = fsm + 4 * MAXCAND * 257 + w * 264;

    int n = g_ncand[q];
    if (n < 0) return;  // handled by k_fixup
    float z2v = g_z2[q];

    // stage z row
    {
        const float4* zsrc = (const float4*)(g_ztf + (size_t)q * D_DIM);
        float4 a = zsrc[lane], b4 = zsrc[lane + 32];
        int d0 = lane * 4;
        zrow[d0] = a.x; zrow[d0 + 1] = a.y; zrow[d0 + 2] = a.z; zrow[d0 + 3] = a.w;
        zrow[d0 + 128] = b4.x; zrow[d0 + 129] = b4.y; zrow[d0 + 130] = b4.z; zrow[d0 + 131] = b4.w;
    }
    // stage candidate rows (coalesced float4 from row-major cb)
    for (int j = 0; j < n; j++) {
        int k = g_cand[q][j];
        const float4* src = (const float4*)(cb + (size_t)k * D_DIM);
        float4 a = src[lane], b4 = src[lane + 32];
        int d0 = lane * 4;
        float* r = rows + j * 257;
        r[d0] = a.x; r[d0 + 1] = a.y; r[d0 + 2] = a.z; r[d0 + 3] = a.w;
        r[d0 + 128] = b4.x; r[d0 + 129] = b4.y; r[d0 + 130] = b4.z; r[d0 + 131] = b4.w;
    }
    __syncwarp();

    float bv = __int_as_float(0x7f800000); int bk = 0x7fffffff;
    if (lane < n) {
        int k = g_cand[q][lane];
        const float* r = rows + lane * 257;
        float acc = 0.f;
#pragma unroll 8
        for (int d = 0; d < D_DIM; d++)
            acc = __fmaf_rn(zrow[d], r[d], acc);   // exact sequential chain, same values
        bv = __fadd_rn(__fsub_rn(z2v, __fmul_rn(2.0f, acc)), g_c2[k]);
        bk = k;
    }
#pragma unroll
    for (int o = 16; o; o >>= 1) {
        float ov = __shfl_xor_sync(0xffffffffu, bv, o);
        int   ok = __shfl_xor_sync(0xffffffffu, bk, o);
        if (ov < bv || (ov == bv && ok < bk)) { bv = ov; bk = ok; }
    }
    if (lane == 0) g_idx[q] = bk;
}

// ---------------- kernel 5: z_q writer (standalone, 32 queries per CTA) ----------------
__global__ __launch_bounds__(256) void k_zq(const float* __restrict__ z,
                                            const float* __restrict__ cb,
                                            float* __restrict__ out, int write_idx) {
    __shared__ int sidx[32];
    __shared__ float smA[32][257];
    const int t = threadIdx.x, lane = t & 31, w = t >> 5;
    const int qb = blockIdx.x * 32;
    const int b = qb >> 10, hw0 = qb & 1023;

    if (t < 32) {
        int ix = g_idx[qb + t];
        sidx[t] = ix;
        if (write_idx) out[(size_t)N_Q * D_DIM + qb + t] = (float)ix;
    }
    __syncthreads();

    // load 32 codebook rows coalesced (4 rows per warp)
#pragma unroll
    for (int r = 0; r < 4; r++) {
        int qq = w * 4 + r;
        const float4* row = (const float4*)(cb + (size_t)sidx[qq] * D_DIM);
        float4 v0 = row[lane];
        float4 v1 = row[lane + 32];
        int d0 = lane * 4;
        smA[qq][d0] = v0.x; smA[qq][d0 + 1] = v0.y; smA[qq][d0 + 2] = v0.z; smA[qq][d0 + 3] = v0.w;
        smA[qq][d0 + 128] = v1.x; smA[qq][d0 + 129] = v1.y; smA[qq][d0 + 130] = v1.z; smA[qq][d0 + 131] = v1.w;
    }
    __syncthreads();

    // write z_q: 32q x 256d, coalesced 128B stores, exact straight-through math
#pragma unroll 4
    for (int i = 0; i < 32; i++) {
        int idx = t + i * 256;
        int d = idx >> 5, qq = idx & 31;
        float cv = smA[qq][d];
        size_t o = (size_t)b * (D_DIM * HW) + (size_t)d * HW + hw0 + qq;
        float zv = z[o];
        out[o] = __fadd_rn(zv, __fsub_rn(cv, zv));
    }
}

// ---------------- launch ----------------
extern "C" void kernel_launch(void* const* d_in, const int* in_sizes, int n_in,
                              void* d_out, int out_size) {
    const float* z_e = (const float*)d_in[0];
    const float* cb  = (const float*)d_in[1];
    float* out = (float*)d_out;

    const size_t smem_mma = 3 * 65536 + 1024;
    const size_t smem_fix = (4 * MAXCAND * 257 + 4 * 264) * sizeof(float);  // ~70KB
    cudaFuncSetAttribute(k_mma, cudaFuncAttributeMaxDynamicSharedMemorySize, (int)smem_mma);
    cudaFuncSetAttribute(k_fixup, cudaFuncAttributeMaxDynamicSharedMemorySize, (int)smem_fix);
    cudaFuncSetAttribute(k_fixup_cb, cudaFuncAttributeMaxDynamicSharedMemorySize, (int)smem_fix);
    int write_idx = (out_size >= (int)(N_Q * D_DIM + N_Q)) ? 1 : 0;

    k_prep_code<<<5120, 256>>>(cb);
    k_prep_z<<<4160, 256>>>(z_e);
    k_mma<<<N_Q / MQ, 512, smem_mma>>>();
    k_fixup<<<N_Q / 4, 128, smem_fix>>>();        // full-rescan (overflow) queries
    k_fixup_cb<<<N_Q / 4, 128, smem_fix>>>(cb);   // candidate queries (the common path)
    k_zq<<<N_Q / 32, 256>>>(z_e, cb, out, write_idx);
}

// round 16
// speedup vs baseline: 5.8332x; 5.8332x over previous
#include <cuda_runtime.h>
#include <cuda_bf16.h>
#include <cstdint>

#define K_CODES 8192
#define D_DIM   256
#define N_Q     16384
#define HW      1024
#define MQ      128
#define CCH     128
#define NCHUNKS (K_CODES / CCH)
#define WIN     2e-4f
#define MAXCAND 16
#define RESCAN_BLOCKS 48

// ---------------- device scratch ----------------
__device__ __nv_bfloat16 g_ztb[(size_t)N_Q * D_DIM];
__device__ float g_ztf[(size_t)N_Q * D_DIM];
__device__ __nv_bfloat16 g_cbb[(size_t)K_CODES * D_DIM];
__device__ float g_cbT[(size_t)D_DIM * K_CODES];
__device__ float g_c2[K_CODES];
__device__ float g_z2[N_Q];
__device__ int   g_ncand[N_Q];
__device__ int   g_cand[N_Q][MAXCAND];
__device__ int   g_idx[N_Q];
__device__ int   g_ovf_count;
__device__ int   g_ovf_list[N_Q];

// ---------------- asm helpers ----------------
__device__ __forceinline__ uint32_t sm_u32(const void* p) {
    uint32_t a;
    asm("{ .reg .u64 t; cvta.to.shared.u64 t, %1; cvt.u32.u64 %0, t; }" : "=r"(a) : "l"(p));
    return a;
}
#define CP_ASYNC16(dst, src) \
    asm volatile("cp.async.cg.shared.global [%0], [%1], 16;" :: "r"(dst), "l"(src))
#define CP_COMMIT() asm volatile("cp.async.commit_group;" ::: "memory")
#define CP_WAIT(n)  asm volatile("cp.async.wait_group %0;" :: "n"(n) : "memory")

__device__ __forceinline__ void ldsm_x4(uint32_t& r0, uint32_t& r1, uint32_t& r2,
                                        uint32_t& r3, uint32_t addr) {
    asm volatile("ldmatrix.sync.aligned.m8n8.x4.shared.b16 {%0,%1,%2,%3}, [%4];"
                 : "=r"(r0), "=r"(r1), "=r"(r2), "=r"(r3) : "r"(addr));
}
__device__ __forceinline__ void ldsm_x2(uint32_t& r0, uint32_t& r1, uint32_t addr) {
    asm volatile("ldmatrix.sync.aligned.m8n8.x2.shared.b16 {%0,%1}, [%2];"
                 : "=r"(r0), "=r"(r1) : "r"(addr));
}
__device__ __forceinline__ void mma_bf16(float& d0, float& d1, float& d2, float& d3,
                                         uint32_t a0, uint32_t a1, uint32_t a2, uint32_t a3,
                                         uint32_t b0, uint32_t b1) {
    asm volatile("mma.sync.aligned.m16n8k16.row.col.f32.bf16.bf16.f32 "
                 "{%0,%1,%2,%3},{%4,%5,%6,%7},{%8,%9},{%0,%1,%2,%3};"
                 : "+f"(d0), "+f"(d1), "+f"(d2), "+f"(d3)
                 : "r"(a0), "r"(a1), "r"(a2), "r"(a3), "r"(b0), "r"(b1));
}
__device__ __forceinline__ uint32_t swz(uint32_t r, uint32_t u) {
    return r * 512u + ((u ^ (r & 7u)) << 4);
}

// ---------------- kernel 1: codebook prep ----------------
__global__ void k_prep_code(const float* __restrict__ cb) {
    int bx = blockIdx.x, t = threadIdx.x;
    if (bx < 2048) {
        if (bx == 0 && t == 0) g_ovf_count = 0;   // reset overflow list each replay
        int i = bx * 256 + t;
        float4 v = ((const float4*)cb)[i];
        ((__nv_bfloat162*)g_cbb)[i * 2] =
            __nv_bfloat162(__float2bfloat16(v.x), __float2bfloat16(v.y));
        ((__nv_bfloat162*)g_cbb)[i * 2 + 1] =
            __nv_bfloat162(__float2bfloat16(v.z), __float2bfloat16(v.w));
    } else if (bx < 4096) {
        __shared__ float tile[32][33];
        int bb = bx - 2048;
        int k0 = (bb & 255) * 32, d0 = (bb >> 8) * 32;
        int tx = t & 31, ty = t >> 5;
#pragma unroll
        for (int j = 0; j < 32; j += 8)
            tile[ty + j][tx] = cb[(size_t)(k0 + ty + j) * D_DIM + d0 + tx];
        __syncthreads();
#pragma unroll
        for (int j = 0; j < 32; j += 8)
            g_cbT[(size_t)(d0 + ty + j) * K_CODES + k0 + tx] = tile[tx][ty + j];
    } else {
        // exact c2 (proven round-1 arithmetic)
        int w = ((bx - 4096) * 256 + t) >> 5;
        int lane = t & 31;
        if (w >= K_CODES) return;
        float s = 0.f;
#pragma unroll
        for (int i = 0; i < 8; i++) {
            float v = cb[(size_t)w * D_DIM + lane + i * 32];
            s = __fadd_rn(s, __fmul_rn(v, v));
        }
#pragma unroll
        for (int o = 16; o; o >>= 1) s = __fadd_rn(s, __shfl_xor_sync(0xffffffffu, s, o));
        if (lane == 0) g_c2[w] = s;
    }
}

// ---------------- kernel 2: z prep + exact z2 ----------------
__global__ void k_prep_z(const float* __restrict__ z) {
    int bx = blockIdx.x, t = threadIdx.x;
    if (bx < 4096) {
        __shared__ float tile[32][33];
        int h0 = (bx & 31) * 32, d0 = ((bx >> 5) & 7) * 32, b = bx >> 8;
        int tx = t & 31, ty = t >> 5;
#pragma unroll
        for (int j = 0; j < 32; j += 8)
            tile[ty + j][tx] = z[(size_t)(b * D_DIM + d0 + ty + j) * HW + h0 + tx];
        __syncthreads();
#pragma unroll
        for (int j = 0; j < 32; j += 8) {
            int q = b * HW + h0 + ty + j, d = d0 + tx;
            float vv = tile[tx][ty + j];
            g_ztf[(size_t)q * D_DIM + d] = vv;
            g_ztb[(size_t)q * D_DIM + d] = __float2bfloat16(vv);
        }
    } else {
        // exact z2 (proven round-1 arithmetic)
        int q = (bx - 4096) * 256 + t;
        int b = q >> 10, hw = q & 1023;
        const float* p = z + (size_t)b * (D_DIM * HW) + hw;
        float s = 0.f;
        for (int d = 0; d < D_DIM; d++) {
            float v = p[(size_t)d * HW];
            s = __fadd_rn(s, __fmul_rn(v, v));
        }
        g_z2[q] = s;
    }
}

// ---------------- kernel 3: main HMMA (unchanged; 278us measured) ----------------
__global__ __launch_bounds__(512, 1) void k_mma() {
    extern __shared__ char sraw[];
    uint32_t raw32 = sm_u32(sraw);
    uint32_t pad = (1024u - (raw32 & 1023u)) & 1023u;
    char* base = sraw + pad;
    const uint32_t sA = raw32 + pad;
    const uint32_t sB0 = sA + 65536u, sB1 = sB0 + 65536u;

    const int t = threadIdx.x, lane = t & 31, w = t >> 5;
    const int mw = w >> 2;
    const int nw = w & 3;
    const int q0 = blockIdx.x * MQ;

    {
        const char* src = (const char*)(g_cbb);
#pragma unroll
        for (int i = 0; i < 8; i++) {
            int idx = i * 512 + t;
            uint32_t r = (uint32_t)(idx >> 5), u = (uint32_t)(idx & 31);
            CP_ASYNC16(sB0 + swz(r, u), src + (size_t)idx * 16);
        }
        CP_COMMIT();
    }
    {
        const int4* src = (const int4*)(g_ztb + (size_t)q0 * D_DIM);
#pragma unroll
        for (int i = 0; i < 8; i++) {
            int idx = i * 512 + t;
            uint32_t r = (uint32_t)(idx >> 5), u = (uint32_t)(idx & 31);
            *(int4*)(base + swz(r, u)) = src[idx];
        }
    }

    float v1[4], v2[4], v3[4];
    int   k1[4], k2[4], k3[4];
#pragma unroll
    for (int i = 0; i < 4; i++) {
        v1[i] = __int_as_float(0x7f800000); v2[i] = v1[i]; v3[i] = v1[i];
        k1[i] = 0x7fffffff; k2[i] = k1[i]; k3[i] = k1[i];
    }

    uint32_t aRow[2], aR7[2];
#pragma unroll
    for (int mi = 0; mi < 2; mi++) {
        uint32_t r = (uint32_t)(mw * 32 + mi * 16 + (lane & 15));
        aRow[mi] = sA + r * 512u;
        aR7[mi] = r & 7u;
    }
    const uint32_t aU = (uint32_t)(lane >> 4);
    const uint32_t bRl = (uint32_t)(nw * 32 + (lane & 7));
    const uint32_t bU = (uint32_t)((lane >> 3) & 1);

    for (int ch = 0; ch < NCHUNKS; ch++) {
        if (ch + 1 < NCHUNKS) {
            uint32_t dstB = ((ch + 1) & 1) ? sB1 : sB0;
            const char* src = (const char*)(g_cbb + (size_t)(ch + 1) * CCH * D_DIM);
#pragma unroll
            for (int i = 0; i < 8; i++) {
                int idx = i * 512 + t;
                uint32_t r = (uint32_t)(idx >> 5), u = (uint32_t)(idx & 31);
                CP_ASYNC16(dstB + swz(r, u), src + (size_t)idx * 16);
            }
            CP_COMMIT();
            CP_WAIT(1);
        } else {
            CP_WAIT(0);
        }
        __syncthreads();

        const uint32_t sB = (ch & 1) ? sB1 : sB0;
        float acc[2][4][4];
#pragma unroll
        for (int mi = 0; mi < 2; mi++)
#pragma unroll
            for (int ni = 0; ni < 4; ni++)
#pragma unroll
                for (int e = 0; e < 4; e++) acc[mi][ni][e] = 0.f;

#pragma unroll
        for (int kk = 0; kk < 16; kk++) {
            uint32_t au = (uint32_t)(kk * 2) + aU;
            uint32_t af[2][4];
#pragma unroll
            for (int mi = 0; mi < 2; mi++)
                ldsm_x4(af[mi][0], af[mi][1], af[mi][2], af[mi][3],
                        aRow[mi] + ((au ^ aR7[mi]) << 4));
            uint32_t bu = (uint32_t)(kk * 2) + bU;
            uint32_t bf[4][2];
#pragma unroll
            for (int ni = 0; ni < 4; ni++) {
                uint32_t r = bRl + (uint32_t)(ni * 8);
                ldsm_x2(bf[ni][0], bf[ni][1], sB + r * 512u + ((bu ^ (r & 7u)) << 4));
            }
#pragma unroll
            for (int mi = 0; mi < 2; mi++)
#pragma unroll
                for (int ni = 0; ni < 4; ni++)
                    mma_bf16(acc[mi][ni][0], acc[mi][ni][1], acc[mi][ni][2], acc[mi][ni][3],
                             af[mi][0], af[mi][1], af[mi][2], af[mi][3],
                             bf[ni][0], bf[ni][1]);
        }

        const int kb = ch * CCH + nw * 32 + (lane & 3) * 2;
#pragma unroll
        for (int ni = 0; ni < 4; ni++) {
            float2 c2v = *(const float2*)(g_c2 + kb + ni * 8);
            int c0 = kb + ni * 8, c1 = c0 + 1;
#pragma unroll
            for (int mi = 0; mi < 2; mi++) {
#pragma unroll
                for (int half = 0; half < 2; half++) {
                    int sl = mi * 2 + half;
                    float s0 = __fmaf_rn(-2.f, acc[mi][ni][half * 2], c2v.x);
                    float s1 = __fmaf_rn(-2.f, acc[mi][ni][half * 2 + 1], c2v.y);
                    if (s0 < v3[sl]) {
                        if (s0 < v1[sl]) { v3[sl]=v2[sl];k3[sl]=k2[sl]; v2[sl]=v1[sl];k2[sl]=k1[sl]; v1[sl]=s0;k1[sl]=c0; }
                        else if (s0 < v2[sl]) { v3[sl]=v2[sl];k3[sl]=k2[sl]; v2[sl]=s0;k2[sl]=c0; }
                        else { v3[sl]=s0;k3[sl]=c0; }
                    }
                    if (s1 < v3[sl]) {
                        if (s1 < v1[sl]) { v3[sl]=v2[sl];k3[sl]=k2[sl]; v2[sl]=v1[sl];k2[sl]=k1[sl]; v1[sl]=s1;k1[sl]=c1; }
                        else if (s1 < v2[sl]) { v3[sl]=v2[sl];k3[sl]=k2[sl]; v2[sl]=s1;k2[sl]=c1; }
                        else { v3[sl]=s1;k3[sl]=c1; }
                    }
                }
            }
        }
        __syncthreads();
    }

    float2* cand = (float2*)(base + 65536);
#pragma unroll
    for (int sl = 0; sl < 4; sl++) {
        int ql = mw * 32 + (sl >> 1) * 16 + (sl & 1) * 8 + (lane >> 2);
        int e = nw * 12 + (lane & 3) * 3;
        cand[ql * 48 + e]     = make_float2(v1[sl], __int_as_float(k1[sl]));
        cand[ql * 48 + e + 1] = make_float2(v2[sl], __int_as_float(k2[sl]));
        cand[ql * 48 + e + 2] = make_float2(v3[sl], __int_as_float(k3[sl]));
    }
    __syncthreads();
    if (t < MQ) {
        float m1 = __int_as_float(0x7f800000);
#pragma unroll
        for (int e = 0; e < 48; e++) m1 = fminf(m1, cand[t * 48 + e].x);
        float lim = m1 + WIN;
        int overflow = 0;
#pragma unroll
        for (int e = 2; e < 48; e += 3) overflow |= (cand[t * 48 + e].x <= lim);
        int q = q0 + t;
        int n = 0;
        if (!overflow) {
#pragma unroll
            for (int e = 0; e < 48; e++) {
                if ((e % 3) == 2) continue;
                float2 c = cand[t * 48 + e];
                if (c.x <= lim && n < MAXCAND) g_cand[q][n++] = __float_as_int(c.y);
                else if (c.x <= lim) overflow = 1;
            }
        }
        g_ncand[q] = overflow ? -1 : n;
    }
}

// ---------------- kernel 4: candidate fixup (warp/query) + overflow list ----------------
__global__ void k_fixup() {
    int q = (blockIdx.x * blockDim.x + threadIdx.x) >> 5;
    int lane = threadIdx.x & 31;
    if (q >= N_Q) return;
    int n = g_ncand[q];
    if (n < 0) {
        if (lane == 0) {
            int slot = atomicAdd(&g_ovf_count, 1);
            g_ovf_list[slot] = q;
        }
        return;
    }
    const float* zr = g_ztf + (size_t)q * D_DIM;
    float z2v = g_z2[q];
    float bv = __int_as_float(0x7f800000); int bk = 0x7fffffff;
    if (lane < n) {
        int k = g_cand[q][lane];
        float acc = 0.f;
#pragma unroll 8
        for (int d = 0; d < D_DIM; d++)
            acc = __fmaf_rn(zr[d], g_cbT[(size_t)d * K_CODES + k], acc);  // exact chain
        bv = __fadd_rn(__fsub_rn(z2v, __fmul_rn(2.0f, acc)), g_c2[k]);
        bk = k;
    }
#pragma unroll
    for (int o = 16; o; o >>= 1) {
        float ov = __shfl_xor_sync(0xffffffffu, bv, o);
        int   ok = __shfl_xor_sync(0xffffffffu, bk, o);
        if (ov < bv || (ov == bv && ok < bk)) { bv = ov; bk = ok; }
    }
    if (lane == 0) g_idx[q] = bk;
}

// ---------------- kernel 5: block-cooperative exact rescan for overflow queries ----------------
__global__ __launch_bounds__(256) void k_rescan() {
    __shared__ float sz[D_DIM];
    __shared__ float2 sred[8];
    const int t = threadIdx.x, lane = t & 31, w = t >> 5;
    int count = g_ovf_count;
    for (int li = blockIdx.x; li < count; li += RESCAN_BLOCKS) {
        int q = g_ovf_list[li];
        sz[t] = g_ztf[(size_t)q * D_DIM + t];
        __syncthreads();
        float z2v = g_z2[q];
        float bv = __int_as_float(0x7f800000); int bk = 0x7fffffff;
        // thread t handles codes k = t + 256*j, ascending; 4-chain ILP groups
        for (int g = 0; g < 32; g += 4) {
            int ka = t + (g + 0) * 256, kb2 = t + (g + 1) * 256,
                kc = t + (g + 2) * 256, kd = t + (g + 3) * 256;
            float a0 = 0.f, a1 = 0.f, a2 = 0.f, a3 = 0.f;
#pragma unroll 8
            for (int d = 0; d < D_DIM; d++) {
                float zv = sz[d];
                const float* row = g_cbT + (size_t)d * K_CODES;
                a0 = __fmaf_rn(zv, row[ka], a0);
                a1 = __fmaf_rn(zv, row[kb2], a1);
                a2 = __fmaf_rn(zv, row[kc], a2);
                a3 = __fmaf_rn(zv, row[kd], a3);
            }
            float d0 = __fadd_rn(__fsub_rn(z2v, __fmul_rn(2.0f, a0)), g_c2[ka]);
            float d1 = __fadd_rn(__fsub_rn(z2v, __fmul_rn(2.0f, a1)), g_c2[kb2]);
            float d2 = __fadd_rn(__fsub_rn(z2v, __fmul_rn(2.0f, a2)), g_c2[kc]);
            float d3 = __fadd_rn(__fsub_rn(z2v, __fmul_rn(2.0f, a3)), g_c2[kd]);
            // ascending k within thread: strict < keeps lowest index
            if (d0 < bv) { bv = d0; bk = ka; }
            if (d1 < bv) { bv = d1; bk = kb2; }
            if (d2 < bv) { bv = d2; bk = kc; }
            if (d3 < bv) { bv = d3; bk = kd; }
        }
        // warp reduce with lowest-index tie rule
#pragma unroll
        for (int o = 16; o; o >>= 1) {
            float ov = __shfl_xor_sync(0xffffffffu, bv, o);
            int   ok = __shfl_xor_sync(0xffffffffu, bk, o);
            if (ov < bv || (ov == bv && ok < bk)) { bv = ov; bk = ok; }
        }
        if (lane == 0) sred[w] = make_float2(bv, __int_as_float(bk));
        __syncthreads();
        if (w == 0) {
            float fv = __int_as_float(0x7f800000); int fk = 0x7fffffff;
            if (lane < 8) { fv = sred[lane].x; fk = __float_as_int(sred[lane].y); }
#pragma unroll
            for (int o = 4; o; o >>= 1) {
                float ov = __shfl_xor_sync(0xffffffffu, fv, o);
                int   ok = __shfl_xor_sync(0xffffffffu, fk, o);
                if (ov < fv || (ov == fv && ok < fk)) { fv = ov; fk = ok; }
            }
            if (lane == 0) g_idx[q] = fk;
        }
        __syncthreads();
    }
}

// ---------------- kernel 6: z_q writer (32 queries per CTA, coalesced) ----------------
__global__ __launch_bounds__(256) void k_zq(const float* __restrict__ z,
                                            const float* __restrict__ cb,
                                            float* __restrict__ out, int write_idx) {
    __shared__ int sidx[32];
    __shared__ float smA[32][257];
    const int t = threadIdx.x, lane = t & 31, w = t >> 5;
    const int qb = blockIdx.x * 32;
    const int b = qb >> 10, hw0 = qb & 1023;

    if (t < 32) {
        int ix = g_idx[qb + t];
        sidx[t] = ix;
        if (write_idx) out[(size_t)N_Q * D_DIM + qb + t] = (float)ix;
    }
    __syncthreads();

#pragma unroll
    for (int r = 0; r < 4; r++) {
        int qq = w * 4 + r;
        const float4* row = (const float4*)(cb + (size_t)sidx[qq] * D_DIM);
        float4 v0 = row[lane];
        float4 v1 = row[lane + 32];
        int d0 = lane * 4;
        smA[qq][d0] = v0.x; smA[qq][d0 + 1] = v0.y; smA[qq][d0 + 2] = v0.z; smA[qq][d0 + 3] = v0.w;
        smA[qq][d0 + 128] = v1.x; smA[qq][d0 + 129] = v1.y; smA[qq][d0 + 130] = v1.z; smA[qq][d0 + 131] = v1.w;
    }
    __syncthreads();

#pragma unroll 4
    for (int i = 0; i < 32; i++) {
        int idx = t + i * 256;
        int d = idx >> 5, qq = idx & 31;
        float cv = smA[qq][d];
        size_t o = (size_t)b * (D_DIM * HW) + (size_t)d * HW + hw0 + qq;
        float zv = z[o];
        out[o] = __fadd_rn(zv, __fsub_rn(cv, zv));
    }
}

// ---------------- launch ----------------
extern "C" void kernel_launch(void* const* d_in, const int* in_sizes, int n_in,
                              void* d_out, int out_size) {
    const float* z_e = (const float*)d_in[0];
    const float* cb  = (const float*)d_in[1];
    float* out = (float*)d_out;

    const size_t smem_mma = 3 * 65536 + 1024;
    cudaFuncSetAttribute(k_mma, cudaFuncAttributeMaxDynamicSharedMemorySize, (int)smem_mma);
    int write_idx = (out_size >= (int)(N_Q * D_DIM + N_Q)) ? 1 : 0;

    k_prep_code<<<5120, 256>>>(cb);
    k_prep_z<<<4160, 256>>>(z_e);
    k_mma<<<N_Q / MQ, 512, smem_mma>>>();
    k_fixup<<<(N_Q * 32) / 256, 256>>>();
    k_rescan<<<RESCAN_BLOCKS, 256>>>();
    k_zq<<<N_Q / 32, 256>>>(z_e, cb, out, write_idx);
}